// round 10
// baseline (speedup 1.0000x reference)
#include <cuda_runtime.h>
#include <cuda_bf16.h>
#include <cstdint>

#define SS 2048
#define DD 64
#define BH 16
#define QT 128          // q rows per block
#define KT 64           // k columns per chunk
#define NCH (SS / KT)   // 32
#define NT 256          // 8 warps
#define SROWB 144       // bf16 tile row stride (72 b16) — conflict-dodging pad
#define EROWF 72        // e-f32 smem row stride in floats (288 B)

// dynamic smem byte offsets
#define QH_O 0
#define QL_O 18432
#define KH_O 36864
#define KL_O 46080
#define VH_O 55296
#define VL_O 64512
#define EF_O 73728      // 128 rows x 288 B = 36864
#define SMEM_DYN 110592

// ---------------- legacy-PTX tensor helpers (valid under .target sm_100) ----
static __device__ __forceinline__ void mma_bf16(float* d, uint32_t a0, uint32_t a1,
                                                uint32_t a2, uint32_t a3,
                                                uint32_t b0, uint32_t b1) {
    asm volatile(
        "mma.sync.aligned.m16n8k16.row.col.f32.bf16.bf16.f32 "
        "{%0,%1,%2,%3}, {%4,%5,%6,%7}, {%8,%9}, {%0,%1,%2,%3};"
        : "+f"(d[0]), "+f"(d[1]), "+f"(d[2]), "+f"(d[3])
        : "r"(a0), "r"(a1), "r"(a2), "r"(a3), "r"(b0), "r"(b1));
}
static __device__ __forceinline__ void ldsm_x4(uint32_t& r0, uint32_t& r1,
                                               uint32_t& r2, uint32_t& r3, uint32_t a) {
    asm volatile("ldmatrix.sync.aligned.m8n8.x4.shared.b16 {%0,%1,%2,%3}, [%4];"
                 : "=r"(r0), "=r"(r1), "=r"(r2), "=r"(r3) : "r"(a));
}
static __device__ __forceinline__ void ldsm_x4_t(uint32_t& r0, uint32_t& r1,
                                                 uint32_t& r2, uint32_t& r3, uint32_t a) {
    asm volatile("ldmatrix.sync.aligned.m8n8.x4.trans.shared.b16 {%0,%1,%2,%3}, [%4];"
                 : "=r"(r0), "=r"(r1), "=r"(r2), "=r"(r3) : "r"(a));
}

// split two floats into packed bf16 hi-pair / lo-pair (x -> low 16 bits)
static __device__ __forceinline__ void split2(float x, float y, uint32_t& hp, uint32_t& lp) {
    __nv_bfloat16 hx = __float2bfloat16(x), hy = __float2bfloat16(y);
    __nv_bfloat16 lx = __float2bfloat16(x - __bfloat162float(hx));
    __nv_bfloat16 ly = __float2bfloat16(y - __bfloat162float(hy));
    hp = (uint32_t)__bfloat16_as_ushort(hx) | ((uint32_t)__bfloat16_as_ushort(hy) << 16);
    lp = (uint32_t)__bfloat16_as_ushort(lx) | ((uint32_t)__bfloat16_as_ushort(ly) << 16);
}

// ============================================================================
__global__ void __launch_bounds__(NT, 2) attn_fused(
    const float* __restrict__ Qg, const float* __restrict__ Kg,
    const float* __restrict__ Vg, const void* __restrict__ Mg,
    float* __restrict__ outV, float* __restrict__ outP)
{
    extern __shared__ char sm[];
    __shared__ int sMaskI32;
    const uint32_t sb = (uint32_t)__cvta_generic_to_shared(sm);

    const int tid = threadIdx.x;
    const int w   = tid >> 5;
    const int lane = tid & 31;
    const int bh = blockIdx.y;
    const int q0 = blockIdx.x * QT;

    const float* Qp = Qg + ((size_t)bh * SS + q0) * DD;
    const float* Kp = Kg + (size_t)bh * SS * DD;
    const float* Vp = Vg + (size_t)bh * SS * DD;
    const size_t moff = ((size_t)bh * SS + q0) * (size_t)SS;
    const int* Mp32 = (const int*)Mg + moff;
    const unsigned char* Mp8 = (const unsigned char*)Mg + moff;
    float* Ep = outP + moff;
    float* Vo = outV + ((size_t)bh * SS + q0) * DD;

    // mask dtype probe (int32 bool-promotion vs raw bytes)
    if (tid < 64) {
        unsigned v = (unsigned)Mp32[tid];
        if (__any_sync(0xffffffffu, v > 1u)) { if ((tid & 31) == 0) sMaskI32 = 0; }
        else                                 { if (tid == 0)        sMaskI32 = 1; }
    }

    // ---- load Q tile -> bf16 hi/lo smem ----
    {
        const int q = tid >> 1, c0 = (tid & 1) * 32;
        const float* src = Qp + (size_t)q * DD + c0;
        char* dh = sm + QH_O + q * SROWB + c0 * 2;
        char* dl = sm + QL_O + q * SROWB + c0 * 2;
#pragma unroll
        for (int c = 0; c < 32; c += 4) {
            float4 v = *(const float4*)(src + c);
            uint32_t h0, l0, h1, l1;
            split2(v.x, v.y, h0, l0);
            split2(v.z, v.w, h1, l1);
            *(uint32_t*)(dh + c * 2) = h0; *(uint32_t*)(dh + c * 2 + 4) = h1;
            *(uint32_t*)(dl + c * 2) = l0; *(uint32_t*)(dl + c * 2 + 4) = l1;
        }
    }

    float accv[32];
#pragma unroll
    for (int i = 0; i < 32; i++) accv[i] = 0.0f;
    float rs1 = 0.0f, rs2 = 0.0f;   // this lane's partial rowsums (rows q1/q2)

    const int fr = lane >> 2;              // frag row 0..7
    const int fc = (lane & 3) * 2;         // frag col (even)
    const int q1 = 16 * w + fr, q2 = q1 + 8;

    const int aRow   = 16 * w + ((lane >> 3) & 1) * 8 + (lane & 7);
    const int aColB  = (lane >> 4) * 8;
    const uint32_t qAddr0 = sb + QH_O + aRow * SROWB + aColB * 2;
    // K x4 lane mapping: matrices {ntpair row 0-7 collo, 0-7 colhi, 8-15 collo, 8-15 colhi}
    const int kRow16 = (lane >> 4) * 8 + (lane & 7);
    const int kCol8  = ((lane >> 3) & 1) * 8;
    const uint32_t kAddr0 = sb + KH_O + kRow16 * SROWB + kCol8 * 2;
    // V trans x4 lane mapping: matrices {k 0-7 nt0, k 8-15 nt0, k 0-7 nt1, k 8-15 nt1}
    const int vRow16 = ((lane >> 3) & 1) * 8 + (lane & 7);
    const int vNtSel = lane >> 4;
    const uint32_t vAddr0 = sb + VH_O + vRow16 * SROWB + vNtSel * 16;

    for (int kt = 0; kt < NCH; kt++) {
        __syncthreads();   // WAR: prev GEMM2 V-reads done before tile overwrite

        // ---- prefetch mask -> 32-bit predicate reg ----
        uint32_t mbits = 0;
        if (sMaskI32) {
#pragma unroll
            for (int nt = 0; nt < 8; nt++) {
                const int kg = kt * KT + nt * 8 + fc;
                int2 ma = *(const int2*)(Mp32 + (size_t)q1 * SS + kg);
                int2 mb = *(const int2*)(Mp32 + (size_t)q2 * SS + kg);
                mbits |= ((ma.x ? 1u : 0u) | (ma.y ? 2u : 0u) |
                          (mb.x ? 4u : 0u) | (mb.y ? 8u : 0u)) << (nt * 4);
            }
        } else {
#pragma unroll
            for (int nt = 0; nt < 8; nt++) {
                const int kg = kt * KT + nt * 8 + fc;
                const unsigned char* pa = Mp8 + (size_t)q1 * SS + kg;
                const unsigned char* pb = Mp8 + (size_t)q2 * SS + kg;
                mbits |= ((pa[0] ? 1u : 0u) | (pa[1] ? 2u : 0u) |
                          (pb[0] ? 4u : 0u) | (pb[1] ? 8u : 0u)) << (nt * 4);
            }
        }

        // ---- load K,V chunk [64 seq][64 d] -> hi/lo smem ----
        {
            const int k = tid >> 2, d0 = (tid & 3) * 16;
            const float* ks = Kp + (size_t)(kt * KT + k) * DD + d0;
            const float* vs = Vp + (size_t)(kt * KT + k) * DD + d0;
            char* kh = sm + KH_O + k * SROWB + d0 * 2;
            char* kl = sm + KL_O + k * SROWB + d0 * 2;
            char* vh = sm + VH_O + k * SROWB + d0 * 2;
            char* vl = sm + VL_O + k * SROWB + d0 * 2;
#pragma unroll
            for (int c = 0; c < 16; c += 4) {
                float4 a = *(const float4*)(ks + c);
                uint32_t h0, l0, h1, l1;
                split2(a.x, a.y, h0, l0); split2(a.z, a.w, h1, l1);
                *(uint32_t*)(kh + c * 2) = h0; *(uint32_t*)(kh + c * 2 + 4) = h1;
                *(uint32_t*)(kl + c * 2) = l0; *(uint32_t*)(kl + c * 2 + 4) = l1;
                float4 b = *(const float4*)(vs + c);
                split2(b.x, b.y, h0, l0); split2(b.z, b.w, h1, l1);
                *(uint32_t*)(vh + c * 2) = h0; *(uint32_t*)(vh + c * 2 + 4) = h1;
                *(uint32_t*)(vl + c * 2) = l0; *(uint32_t*)(vl + c * 2 + 4) = l1;
            }
        }
        __syncthreads();

        // ---- GEMM1: S = Q K^T  (3-term bf16, x4 B loads: two nt per ldsm) ----
        float sf[8][4];
#pragma unroll
        for (int nt = 0; nt < 8; nt++)
#pragma unroll
            for (int j = 0; j < 4; j++) sf[nt][j] = 0.0f;

#pragma unroll
        for (int ks = 0; ks < 4; ks++) {
            uint32_t ah0, ah1, ah2, ah3, al0, al1, al2, al3;
            ldsm_x4(ah0, ah1, ah2, ah3, qAddr0 + ks * 32);
            ldsm_x4(al0, al1, al2, al3, qAddr0 + (QL_O - QH_O) + ks * 32);
#pragma unroll
            for (int ntp = 0; ntp < 4; ntp++) {
                const uint32_t ba = kAddr0 + ntp * (16 * SROWB) + ks * 32;
                uint32_t kh0, kh1, kh2, kh3, kl0, kl1, kl2, kl3;
                ldsm_x4(kh0, kh1, kh2, kh3, ba);
                ldsm_x4(kl0, kl1, kl2, kl3, ba + (KL_O - KH_O));
                mma_bf16(sf[2 * ntp],     ah0, ah1, ah2, ah3, kh0, kh1);
                mma_bf16(sf[2 * ntp],     ah0, ah1, ah2, ah3, kl0, kl1);
                mma_bf16(sf[2 * ntp],     al0, al1, al2, al3, kh0, kh1);
                mma_bf16(sf[2 * ntp + 1], ah0, ah1, ah2, ah3, kh2, kh3);
                mma_bf16(sf[2 * ntp + 1], ah0, ah1, ah2, ah3, kl2, kl3);
                mma_bf16(sf[2 * ntp + 1], al0, al1, al2, al3, kh2, kh3);
            }
        }

        // ---- per k16-slice: mask+scale in regs -> A-frags; e -> smem; GEMM2 ----
#pragma unroll
        for (int ks = 0; ks < 4; ks++) {
            const int n0 = 2 * ks, n1 = 2 * ks + 1;
            const uint32_t mb0 = mbits >> (n0 * 4), mb1 = mbits >> (n1 * 4);
            float a00 = (mb0 & 1) ? -1e9f : sf[n0][0] * 0.125f;
            float a01 = (mb0 & 2) ? -1e9f : sf[n0][1] * 0.125f;
            float a02 = (mb0 & 4) ? -1e9f : sf[n0][2] * 0.125f;
            float a03 = (mb0 & 8) ? -1e9f : sf[n0][3] * 0.125f;
            float a10 = (mb1 & 1) ? -1e9f : sf[n1][0] * 0.125f;
            float a11 = (mb1 & 2) ? -1e9f : sf[n1][1] * 0.125f;
            float a12 = (mb1 & 4) ? -1e9f : sf[n1][2] * 0.125f;
            float a13 = (mb1 & 8) ? -1e9f : sf[n1][3] * 0.125f;

            // e = exp(a): accumulate register rowsums, scatter to smem band
            {
                float e00 = (mb0 & 1) ? 0.f : __expf(a00);
                float e01 = (mb0 & 2) ? 0.f : __expf(a01);
                float e02 = (mb0 & 4) ? 0.f : __expf(a02);
                float e03 = (mb0 & 8) ? 0.f : __expf(a03);
                float e10 = (mb1 & 1) ? 0.f : __expf(a10);
                float e11 = (mb1 & 2) ? 0.f : __expf(a11);
                float e12 = (mb1 & 4) ? 0.f : __expf(a12);
                float e13 = (mb1 & 8) ? 0.f : __expf(a13);
                rs1 += (e00 + e01) + (e10 + e11);
                rs2 += (e02 + e03) + (e12 + e13);
                const int kc0 = n0 * 8 + fc, kc1 = n1 * 8 + fc;
                float* e1p = (float*)(sm + EF_O) + q1 * EROWF;
                float* e2p = (float*)(sm + EF_O) + q2 * EROWF;
                *(float2*)(e1p + kc0) = make_float2(e00, e01);
                *(float2*)(e2p + kc0) = make_float2(e02, e03);
                *(float2*)(e1p + kc1) = make_float2(e10, e11);
                *(float2*)(e2p + kc1) = make_float2(e12, e13);
            }

            // A-fragments for the k16 slice
            uint32_t r0h, r0l, r1h, r1l, r2h, r2l, r3h, r3l;
            split2(a00, a01, r0h, r0l);
            split2(a02, a03, r1h, r1l);
            split2(a10, a11, r2h, r2l);
            split2(a12, a13, r3h, r3l);

#pragma unroll
            for (int ntp = 0; ntp < 4; ntp++) {
                const uint32_t ba = vAddr0 + (ks * 16) * SROWB + ntp * 32;
                uint32_t vh0, vh1, vh2, vh3, vl0, vl1, vl2, vl3;
                ldsm_x4_t(vh0, vh1, vh2, vh3, ba);
                ldsm_x4_t(vl0, vl1, vl2, vl3, ba + (VL_O - VH_O));
                float* d0 = accv + (2 * ntp) * 4;
                float* d1 = accv + (2 * ntp + 1) * 4;
                mma_bf16(d0, r0h, r1h, r2h, r3h, vh0, vh1);
                mma_bf16(d0, r0h, r1h, r2h, r3h, vl0, vl1);
                mma_bf16(d0, r0l, r1l, r2l, r3l, vh0, vh1);
                mma_bf16(d1, r0h, r1h, r2h, r3h, vh2, vh3);
                mma_bf16(d1, r0h, r1h, r2h, r3h, vl2, vl3);
                mma_bf16(d1, r0l, r1l, r2l, r3l, vh2, vh3);
            }
        }

        // ---- coalesced e write (warp-local band; two rows per iteration) ----
        __syncwarp();
        {
            const int half = lane >> 4;       // 0,1
            const int l16  = lane & 15;
#pragma unroll
            for (int rr = 0; rr < 16; rr += 2) {
                const int row = 16 * w + rr + half;
                const float* ep = (const float*)(sm + EF_O) + row * EROWF + l16 * 4;
                float4 e = *(const float4*)ep;
                *(float4*)(Ep + (size_t)row * SS + kt * KT + l16 * 4) = e;
            }
        }
        __syncwarp();   // reads done before next chunk's scatter
    }

    // ---- attn_v store ----
#pragma unroll
    for (int nt = 0; nt < 8; nt++) {
        const int d = nt * 8 + fc;
        *(float2*)(Vo + (size_t)q1 * DD + d) = make_float2(accv[nt * 4 + 0], accv[nt * 4 + 1]);
        *(float2*)(Vo + (size_t)q2 * DD + d) = make_float2(accv[nt * 4 + 2], accv[nt * 4 + 3]);
    }

    // ---- rowsum quad-reduce: lane 4r -> rows 16w+r (rs1), 16w+8+r (rs2) ----
    rs1 += __shfl_xor_sync(0xffffffffu, rs1, 1);
    rs1 += __shfl_xor_sync(0xffffffffu, rs1, 2);
    rs2 += __shfl_xor_sync(0xffffffffu, rs2, 1);
    rs2 += __shfl_xor_sync(0xffffffffu, rs2, 2);

    // ---- softmax normalization: warp-per-row, coalesced, last-written-first ----
#pragma unroll 1
    for (int r = 15; r >= 0; r--) {
        const float s1 = __shfl_sync(0xffffffffu, rs1, (r & 7) * 4);
        const float s2 = __shfl_sync(0xffffffffu, rs2, (r & 7) * 4);
        const float invr = 1.0f / (r < 8 ? s1 : s2);
        float* row = Ep + (size_t)(16 * w + r) * SS;
#pragma unroll 4
        for (int i = 15; i >= 0; i--) {
            float4 v = *(const float4*)(row + (i * 32 + lane) * 4);
            v.x *= invr; v.y *= invr; v.z *= invr; v.w *= invr;
            *(float4*)(row + (i * 32 + lane) * 4) = v;
        }
    }
}

// ============================================================================
extern "C" void kernel_launch(void* const* d_in, const int* in_sizes, int n_in,
                              void* d_out, int out_size)
{
    const float* Q = (const float*)d_in[0];
    const float* K = (const float*)d_in[1];
    const float* V = (const float*)d_in[2];
    const void*  M = d_in[3];

    float* out = (float*)d_out;
    const long long VN = (long long)BH * SS * DD;   // attn_v elements
    float* outV = out;
    float* outP = out + VN;                         // attn_p region

    cudaFuncSetAttribute(attn_fused, cudaFuncAttributeMaxDynamicSharedMemorySize, SMEM_DYN);

    dim3 grid(SS / QT, BH);
    attn_fused<<<grid, NT, SMEM_DYN>>>(Q, K, V, M, outV, outP);
}